// round 1
// baseline (speedup 1.0000x reference)
#include <cuda_runtime.h>
#include <cstddef>

#define CH   128
#define HH   96
#define WW   96
#define HW   9216          // 96*96
#define BATCH 16
#define NOUT 1000

// Scratch (device globals — no runtime allocation allowed)
__device__ float g_mixed[(size_t)BATCH * CH * HW];   // 75.5 MB
__device__ float g_x[(size_t)BATCH * CH * HW];       // 75.5 MB
__device__ float g_pool[BATCH * CH];

// ---------------------------------------------------------------------------
// Channel-mix GEMM: mixed[b,c,p] = sum_i lin[c,i] * xin[b,i,p]
// M=128 (out ch), N=9216 per batch (pixels), K = 64 or 128.
// Block: 128 pixels x 128 channels, 256 threads, 8x8 microtile, BK=16.
// ---------------------------------------------------------------------------
__global__ void mix_gemm(const float* __restrict__ lin,
                         const float* __restrict__ xin,
                         float* __restrict__ out, int K) {
    __shared__ float As[16][128];   // [k][m]  (lin transposed)
    __shared__ float Bs[16][128];   // [k][n]

    const int b     = blockIdx.y;
    const int pbase = blockIdx.x * 128;
    const int tid   = threadIdx.x;
    const int ty    = tid >> 4;     // 0..15  (channel group)
    const int tx    = tid & 15;     // 0..15  (pixel group)

    const float* xb = xin + (size_t)b * K * HW;

    float acc[8][8];
#pragma unroll
    for (int i = 0; i < 8; i++)
#pragma unroll
        for (int j = 0; j < 8; j++) acc[i][j] = 0.f;

    for (int k0 = 0; k0 < K; k0 += 16) {
        // A tile: 128 rows x 16 k  = 512 float4
#pragma unroll
        for (int r = 0; r < 2; r++) {
            int li = tid + r * 256;           // 0..511
            int m  = li >> 2;                 // 0..127
            int kk = (li & 3) * 4;            // 0,4,8,12
            float4 a = *(const float4*)(lin + (size_t)m * K + k0 + kk);
            As[kk + 0][m] = a.x; As[kk + 1][m] = a.y;
            As[kk + 2][m] = a.z; As[kk + 3][m] = a.w;
        }
        // B tile: 16 k x 128 pixels = 512 float4
#pragma unroll
        for (int r = 0; r < 2; r++) {
            int li = tid + r * 256;
            int kk = li >> 5;                 // 0..15
            int n4 = li & 31;                 // 0..31
            *(float4*)&Bs[kk][n4 * 4] =
                *(const float4*)(xb + (size_t)(k0 + kk) * HW + pbase + n4 * 4);
        }
        __syncthreads();

#pragma unroll
        for (int kk = 0; kk < 16; kk++) {
            float ra[8], rb[8];
#pragma unroll
            for (int i = 0; i < 8; i += 4) {
                float4 v = *(const float4*)&As[kk][ty * 8 + i];
                ra[i] = v.x; ra[i+1] = v.y; ra[i+2] = v.z; ra[i+3] = v.w;
            }
#pragma unroll
            for (int j = 0; j < 8; j += 4) {
                float4 v = *(const float4*)&Bs[kk][tx * 8 + j];
                rb[j] = v.x; rb[j+1] = v.y; rb[j+2] = v.z; rb[j+3] = v.w;
            }
#pragma unroll
            for (int i = 0; i < 8; i++)
#pragma unroll
                for (int j = 0; j < 8; j++)
                    acc[i][j] = fmaf(ra[i], rb[j], acc[i][j]);
        }
        __syncthreads();
    }

    float* ob = out + (size_t)b * CH * HW + pbase;
#pragma unroll
    for (int i = 0; i < 8; i++) {
        int m = ty * 8 + i;
#pragma unroll
        for (int j0 = 0; j0 < 8; j0 += 4) {
            float4 v = make_float4(acc[i][j0], acc[i][j0+1], acc[i][j0+2], acc[i][j0+3]);
            *(float4*)(ob + (size_t)m * HW + tx * 8 + j0) = v;
        }
    }
}

// ---------------------------------------------------------------------------
// Affine bilinear sample of mixed (per-channel theta), times analytic box
// weight map (affine sample of ones needs no memory), plus optional residual.
// grid: (36, 128 channels, 16 batch), 256 threads (one output pixel each).
// ---------------------------------------------------------------------------
__global__ void sample_kernel(const float* __restrict__ mixed,
                              const float* __restrict__ geo,
                              const float* __restrict__ box,
                              const float* __restrict__ resid,
                              float* __restrict__ out) {
    const int c = blockIdx.y;
    const int b = blockIdx.z;
    const int p = blockIdx.x * 256 + threadIdx.x;   // 0..9215
    const int h = p / WW;
    const int w = p - h * WW;

    const float gxc = (w + 0.5f) * (2.0f / WW) - 1.0f;
    const float gyc = (h + 0.5f) * (2.0f / HH) - 1.0f;

    // ---- geo sample (gather from mixed) ----
    const float* g = geo + c * 6;
    float gridx = g[0] * gxc + g[1] * gyc + g[2];
    float gridy = g[3] * gxc + g[4] * gyc + g[5];
    float ix = ((gridx + 1.0f) * WW - 1.0f) * 0.5f;
    float iy = ((gridy + 1.0f) * HH - 1.0f) * 0.5f;
    float fx0 = floorf(ix), fy0 = floorf(iy);
    int   x0 = (int)fx0, y0 = (int)fy0;
    float wx1 = ix - fx0, wy1 = iy - fy0;
    float wx0 = 1.0f - wx1, wy0 = 1.0f - wy1;

    const float* plane = mixed + ((size_t)b * CH + c) * HW;
    auto tap = [&](int yi, int xi, float wt) -> float {
        bool v = (xi >= 0) & (xi < WW) & (yi >= 0) & (yi < HH);
        int xc = min(max(xi, 0), WW - 1);
        int yc = min(max(yi, 0), HH - 1);
        return v ? plane[yc * WW + xc] * wt : 0.0f;
    };
    float s = tap(y0,     x0,     wy0 * wx0)
            + tap(y0,     x0 + 1, wy0 * wx1)
            + tap(y0 + 1, x0,     wy1 * wx0)
            + tap(y0 + 1, x0 + 1, wy1 * wx1);

    // ---- box sample of ones (no loads) ----
    const float* bx = box + c * 6;
    float bgx = bx[0] * gxc + bx[1] * gyc + bx[2];
    float bgy = bx[3] * gxc + bx[4] * gyc + bx[5];
    float bix = ((bgx + 1.0f) * WW - 1.0f) * 0.5f;
    float biy = ((bgy + 1.0f) * HH - 1.0f) * 0.5f;
    float bfx0 = floorf(bix), bfy0 = floorf(biy);
    int   bx0 = (int)bfx0, by0 = (int)bfy0;
    float bwx1 = bix - bfx0, bwy1 = biy - bfy0;
    float bwx0 = 1.0f - bwx1, bwy0 = 1.0f - bwy1;

    auto vmask = [](int yi, int xi) -> float {
        return ((xi >= 0) & (xi < WW) & (yi >= 0) & (yi < HH)) ? 1.0f : 0.0f;
    };
    float bval = vmask(by0,     bx0)     * bwy0 * bwx0
               + vmask(by0,     bx0 + 1) * bwy0 * bwx1
               + vmask(by0 + 1, bx0)     * bwy1 * bwx0
               + vmask(by0 + 1, bx0 + 1) * bwy1 * bwx1;

    const size_t idx = ((size_t)b * CH + c) * HW + p;
    float v = s * bval;
    if (resid) v += resid[idx];
    out[idx] = v;
}

// ---------------------------------------------------------------------------
// Global average pool: one block per (b,c) plane.
// ---------------------------------------------------------------------------
__global__ void pool_kernel(const float* __restrict__ feat,
                            float* __restrict__ pooled) {
    const int bc = blockIdx.x;             // 0..2047
    const float* plane = feat + (size_t)bc * HW;
    float s = 0.f;
    for (int i = threadIdx.x; i < HW; i += 256) s += plane[i];
    // warp + block reduce
    for (int o = 16; o > 0; o >>= 1) s += __shfl_down_sync(0xffffffffu, s, o);
    __shared__ float sm[8];
    if ((threadIdx.x & 31) == 0) sm[threadIdx.x >> 5] = s;
    __syncthreads();
    if (threadIdx.x == 0) {
        float t = 0.f;
        for (int i = 0; i < 8; i++) t += sm[i];
        pooled[bc] = t * (1.0f / HW);
    }
}

// ---------------------------------------------------------------------------
// Dense head: logits[b,o] = pooled[b,:] . dense_w[o,:] + dense_b[o]
// ---------------------------------------------------------------------------
__global__ void dense_kernel(const float* __restrict__ pooled,
                             const float* __restrict__ dw,
                             const float* __restrict__ db,
                             float* __restrict__ logits) {
    int gid = blockIdx.x * 256 + threadIdx.x;
    if (gid >= BATCH * NOUT) return;
    int o = gid % NOUT;
    int b = gid / NOUT;
    const float* pr = pooled + b * CH;
    const float* wr = dw + (size_t)o * CH;
    float s = 0.f;
#pragma unroll 16
    for (int c = 0; c < CH; c++) s = fmaf(pr[c], wr[c], s);
    logits[gid] = s + db[o];
}

// ---------------------------------------------------------------------------
extern "C" void kernel_launch(void* const* d_in, const int* in_sizes, int n_in,
                              void* d_out, int out_size) {
    const float* x       = (const float*)d_in[0];  // [16,64,96,96]
    const float* in_geo  = (const float*)d_in[1];  // [128,2,3]
    const float* in_box  = (const float*)d_in[2];
    const float* in_lin  = (const float*)d_in[3];  // [128,64]
    const float* lay_geo = (const float*)d_in[4];  // [4,128,2,3]
    const float* lay_box = (const float*)d_in[5];
    const float* lay_lin = (const float*)d_in[6];  // [4,128,128]
    const float* dense_w = (const float*)d_in[7];  // [1000,128]
    const float* dense_b = (const float*)d_in[8];  // [1000]

    float* out    = (float*)d_out;
    float* logits = out;                 // [16,1000]
    float* feat   = out + BATCH * NOUT;  // [16,128,96,96]

    float *mixed_p, *x_p, *pool_p;
    cudaGetSymbolAddress((void**)&mixed_p, g_mixed);
    cudaGetSymbolAddress((void**)&x_p,     g_x);
    cudaGetSymbolAddress((void**)&pool_p,  g_pool);

    dim3 ggrid(HW / 128, BATCH);          // (72, 16)
    dim3 sgrid(HW / 256, CH, BATCH);      // (36, 128, 16)

    // input layer (K=64, no residual)
    mix_gemm<<<ggrid, 256>>>(in_lin, x, mixed_p, 64);
    sample_kernel<<<sgrid, 256>>>(mixed_p, in_geo, in_box, nullptr, x_p);

    // 4 residual layers (K=128)
    for (int i = 0; i < 4; i++) {
        mix_gemm<<<ggrid, 256>>>(lay_lin + (size_t)i * CH * CH, x_p, mixed_p, CH);
        float* dst = (i == 3) ? feat : x_p;
        sample_kernel<<<sgrid, 256>>>(mixed_p, lay_geo + (size_t)i * CH * 6,
                                      lay_box + (size_t)i * CH * 6, x_p, dst);
    }

    pool_kernel<<<BATCH * CH, 256>>>(feat, pool_p);
    dense_kernel<<<(BATCH * NOUT + 255) / 256, 256>>>(pool_p, dense_w, dense_b, logits);
}